// round 2
// baseline (speedup 1.0000x reference)
#include <cuda_runtime.h>
#include <cstdint>

// ---------------- packed f32x2 helpers (Blackwell) ----------------
__device__ __forceinline__ unsigned long long f2x_mul(unsigned long long a, unsigned long long b) {
    unsigned long long d;
    asm("mul.rn.f32x2 %0, %1, %2;" : "=l"(d) : "l"(a), "l"(b));
    return d;
}
__device__ __forceinline__ unsigned long long f2x_fma(unsigned long long a, unsigned long long b, unsigned long long c) {
    unsigned long long d;
    asm("fma.rn.f32x2 %0, %1, %2, %3;" : "=l"(d) : "l"(a), "l"(b), "l"(c));
    return d;
}
__device__ __forceinline__ unsigned long long f2x_add(unsigned long long a, unsigned long long b) {
    unsigned long long d;
    asm("add.rn.f32x2 %0, %1, %2;" : "=l"(d) : "l"(a), "l"(b));
    return d;
}
__device__ __forceinline__ unsigned long long f2x_pack(float lo, float hi) {
    unsigned long long d;
    asm("mov.b64 %0, {%1, %2};" : "=l"(d) : "r"(__float_as_uint(lo)), "r"(__float_as_uint(hi)));
    return d;
}
__device__ __forceinline__ void f2x_unpack(float& lo, float& hi, unsigned long long v) {
    unsigned int l, h;
    asm("mov.b64 {%0, %1}, %2;" : "=r"(l), "=r"(h) : "l"(v));
    lo = __uint_as_float(l);
    hi = __uint_as_float(h);
}

// Cody-Waite reduction of phase to ~[-pi, pi]; exact for |phase| <~ 25000
__device__ __forceinline__ float red2pi(float ph) {
    float q = rintf(ph * 0.15915494309f);       // 1/(2*pi)
    ph = fmaf(q, -6.28125f, ph);                // 2*pi hi (12-bit mantissa, product exact)
    ph = fmaf(q, -1.93530717e-3f, ph);          // 2*pi lo
    return ph;
}

// ---------------- main kernel: one block = (head h, half of L) ----------------
// Block = 64 threads, grid = 2*H. Block b handles h = b>>1, l in
// [half*1024, half*1024+1024). Thread t computes out[h, base + 64k],
// k = 0..STEPS-1, via the real 2nd-order recurrence per mode n:
//   u_k = a*u_{k-1} + b*u_{k-2},  a = 2 Re(W), b = -|W|^2, W = exp(dtA * 64).
// 32 modes packed as 16 f32x2 lanes. Two independent accumulator chains.
template <int STEPS>
__global__ __launch_bounds__(64, 10) void s4d_kernel(
    const float* __restrict__ log_dt,
    const float* __restrict__ Cr,          // (H, 32, 2)
    const float* __restrict__ logAre,      // (H, 32)
    const float* __restrict__ Aimag,       // (H, 32)
    float* __restrict__ out, int L)
{
    const int h    = blockIdx.x >> 1;
    const int half = blockIdx.x & 1;
    const int tid  = threadIdx.x;

    __shared__ float4 sp1[32];  // {a, b, winv_re, winv_im}
    __shared__ float4 sp2[32];  // {cd_re, cd_im, dta_re, dta_im}

    if (tid < 32) {
        const int n = tid;
        const float dt  = __expf(log_dt[h]);
        const float Are = -__expf(logAre[h * 32 + n]);
        const float Ai  = Aimag[h * 32 + n];
        const float dre = Are * dt;
        const float dim = Ai * dt;

        // exp(dtA) (small args: |dim| <= ~10)
        float s1, c1;
        __sincosf(dim, &s1, &c1);
        const float e1 = __expf(dre);
        const float numre = fmaf(e1, c1, -1.0f);
        const float numim = e1 * s1;

        // Cd = Cc * (exp(dtA) - 1) / A  =  Cc * num * conj(A) / |A|^2
        const float inv  = __frcp_rn(fmaf(Are, Are, Ai * Ai));
        const float ccre = Cr[(h * 32 + n) * 2 + 0];
        const float ccim = Cr[(h * 32 + n) * 2 + 1];
        const float tre = ccre * numre - ccim * numim;
        const float tim = ccre * numim + ccim * numre;
        const float cdre = (tre * Are + tim * Ai) * inv;
        const float cdim = (tim * Are - tre * Ai) * inv;

        // W = exp(dtA * 64)
        const float phT = red2pi(dim * 64.0f);
        float sT, cT;
        __sincosf(phT, &sT, &cT);
        const float eT  = __expf(dre * 64.0f);   // >= exp(-3.2), no underflow
        const float Wre = eT * cT;
        const float Wim = eT * sT;
        const float ib  = __frcp_rn(eT * eT);    // 1/|W|^2

        sp1[n] = make_float4(2.0f * Wre, -eT * eT, Wre * ib, -Wim * ib);
        sp2[n] = make_float4(cdre, cdim, dre, dim);
    }
    __syncthreads();

    unsigned long long X1[16], X2[16], A2[16], B2[16];
    const int   base = half * 1024 + tid;
    const float tf   = (float)base;

    #pragma unroll
    for (int p = 0; p < 16; p++) {
        float x1v[2], x2v[2], av[2], bv[2];
        #pragma unroll
        for (int j = 0; j < 2; j++) {
            const int n = 2 * p + j;
            const float4 q1 = sp1[n];
            const float4 q2 = sp2[n];
            // z = Cd * exp(dtA * base)
            const float ph = red2pi(q2.w * tf);
            float s, c;
            __sincosf(ph, &s, &c);
            const float r  = __expf(q2.z * tf);   // >= exp(-55), no underflow
            const float er = r * c;
            const float ei = r * s;
            const float zre = q2.x * er - q2.y * ei;
            const float zim = q2.x * ei + q2.y * er;
            x1v[j] = zre;                              // s(base)
            x2v[j] = zre * q1.z - zim * q1.w;          // s(base - 64) = Re(z * W^-1)
            av[j]  = q1.x;
            bv[j]  = q1.y;
        }
        X1[p] = f2x_pack(x1v[0], x1v[1]);
        X2[p] = f2x_pack(x2v[0], x2v[1]);
        A2[p] = f2x_pack(av[0],  av[1]);
        B2[p] = f2x_pack(bv[0],  bv[1]);
    }

    float* op = out + (size_t)h * L + base;

    #pragma unroll
    for (int k = 0; k < STEPS; k++) {
        unsigned long long acc0 = 0ull;  // packed (0.0f, 0.0f)
        unsigned long long acc1 = 0ull;
        #pragma unroll
        for (int p = 0; p < 16; p += 2) {
            acc0 = f2x_add(acc0, X1[p]);
            {
                const unsigned long long t  = f2x_mul(B2[p], X2[p]);
                const unsigned long long xn = f2x_fma(A2[p], X1[p], t);
                X2[p] = X1[p];
                X1[p] = xn;
            }
            acc1 = f2x_add(acc1, X1[p + 1]);
            {
                const unsigned long long t  = f2x_mul(B2[p + 1], X2[p + 1]);
                const unsigned long long xn = f2x_fma(A2[p + 1], X1[p + 1], t);
                X2[p + 1] = X1[p + 1];
                X1[p + 1] = xn;
            }
        }
        const unsigned long long acc = f2x_add(acc0, acc1);
        float lo, hi;
        f2x_unpack(lo, hi, acc);
        op[(size_t)k * 64] = 2.0f * (lo + hi);
    }
}

// ---------------- generic fallback (any H, N2, L) ----------------
__global__ void s4d_fallback(
    const float* __restrict__ log_dt,
    const float* __restrict__ Cr,
    const float* __restrict__ logAre,
    const float* __restrict__ Aimag,
    float* __restrict__ out, int H, int N2, int L)
{
    const long long idx = (long long)blockIdx.x * blockDim.x + threadIdx.x;
    if (idx >= (long long)H * L) return;
    const int h = (int)(idx / L);
    const int l = (int)(idx % L);
    const float dt = __expf(log_dt[h]);
    const float lf = (float)l;
    float acc = 0.0f;
    for (int n = 0; n < N2; n++) {
        const float Are = -__expf(logAre[h * N2 + n]);
        const float Ai  = Aimag[h * N2 + n];
        const float dre = Are * dt;
        const float dim = Ai * dt;
        float s1, c1;
        __sincosf(dim, &s1, &c1);
        const float e1 = __expf(dre);
        const float numre = fmaf(e1, c1, -1.0f);
        const float numim = e1 * s1;
        const float inv  = __frcp_rn(fmaf(Are, Are, Ai * Ai));
        const float ccre = Cr[(h * N2 + n) * 2 + 0];
        const float ccim = Cr[(h * N2 + n) * 2 + 1];
        const float tre = ccre * numre - ccim * numim;
        const float tim = ccre * numim + ccim * numre;
        const float cdre = (tre * Are + tim * Ai) * inv;
        const float cdim = (tim * Are - tre * Ai) * inv;
        const float ph = red2pi(dim * lf);
        float s, c;
        __sincosf(ph, &s, &c);
        const float r = __expf(dre * lf);
        acc += r * (cdre * c - cdim * s);
    }
    out[idx] = 2.0f * acc;
}

extern "C" void kernel_launch(void* const* d_in, const int* in_sizes, int n_in,
                              void* d_out, int out_size)
{
    const float* log_dt = (const float*)d_in[0];
    const float* Cr     = (const float*)d_in[1];
    const float* lar    = (const float*)d_in[2];
    const float* aim    = (const float*)d_in[3];
    float* out = (float*)d_out;

    const int H  = in_sizes[0];
    const int N2 = (H > 0) ? in_sizes[2] / H : 0;
    const int L  = (H > 0) ? out_size / H : 0;

    if (N2 == 32 && L == 2048) {
        s4d_kernel<16><<<H * 2, 64>>>(log_dt, Cr, lar, aim, out, L);
    } else {
        const long long total = (long long)H * L;
        const int blocks = (int)((total + 127) / 128);
        s4d_fallback<<<blocks, 128>>>(log_dt, Cr, lar, aim, out, H, N2, L);
    }
}

// round 4
// speedup vs baseline: 1.2620x; 1.2620x over previous
#include <cuda_runtime.h>
#include <cuda_bf16.h>
#include <mma.h>
#include <cstdint>

using namespace nvcuda;

__device__ __forceinline__ float2 cmul(float2 a, float2 b) {
    return make_float2(fmaf(a.x, b.x, -a.y * b.y), fmaf(a.x, b.y, a.y * b.x));
}

// ============================ WMMA kernel ============================
// One CTA (256 thr) per head h. out[h, 64j+i] = 2*sum_n [ReP*ReW^j - ImP*ImW^j]
//   P = Cd*E^i, E = exp(dtA), W = E^64.
// Real GEMM  M=64 (i) x N=32 (j) x K=64 (re|im of 32 modes):
//   A[i][n]    = Re(P_i,n)   A[i][32+n] = Im(P_i,n)       (row-major, ld=72)
//   B[k][j]:  col-major as Bsm[j*72 + k]: k=n -> Re(W^j),  k=32+n -> -Im(W^j)
// bf16 hi/lo split, 3 passes: Ahi*Bhi + Alo*Bhi + Ahi*Blo  (lo*lo dropped).

static constexpr int LDA = 72;   // padded to kill ldmatrix bank conflicts

__global__ __launch_bounds__(256)
void s4d_wmma(const float* __restrict__ log_dt,
              const float* __restrict__ Cr,
              const float* __restrict__ logAre,
              const float* __restrict__ Aimag,
              float* __restrict__ out)
{
    __shared__ __nv_bfloat16 Ahi[64 * LDA];   // 9216 B
    __shared__ __nv_bfloat16 Alo[64 * LDA];   // 9216 B
    __shared__ __nv_bfloat16 Bhi[32 * LDA];   // 4608 B
    __shared__ __nv_bfloat16 Blo[32 * LDA];   // 4608 B
    __shared__ float2 cst[32 * 9];            // 2304 B

    const int h   = blockIdx.x;
    const int tid = threadIdx.x;
    const int wid = tid >> 5;

    // ---- per-mode constants (threads 0-31) ----
    if (tid < 32) {
        const int n = tid;
        const float dt  = __expf(log_dt[h]);
        const float Are = -__expf(logAre[h * 32 + n]);
        const float Ai  = Aimag[h * 32 + n];
        const float dre = Are * dt;
        const float dim = Ai * dt;                 // |dim| <= ~9.8, sincos fine
        float s, c;
        __sincosf(dim, &s, &c);
        const float e1 = __expf(dre);
        const float2 E = make_float2(e1 * c, e1 * s);
        const float inv = __frcp_rn(fmaf(Are, Are, Ai * Ai));
        const float ccre = Cr[(h * 32 + n) * 2 + 0];
        const float ccim = Cr[(h * 32 + n) * 2 + 1];
        const float numre = E.x - 1.0f, numim = E.y;
        const float tre = ccre * numre - ccim * numim;
        const float tim = ccre * numim + ccim * numre;
        const float2 Cd = make_float2((tre * Are + tim * Ai) * inv,
                                      (tim * Are - tre * Ai) * inv);
        const float2 E2  = cmul(E, E);
        const float2 E4  = cmul(E2, E2);
        const float2 E8  = cmul(E4, E4);
        const float2 E16 = cmul(E8, E8);
        const float2 E32 = cmul(E16, E16);
        const float2 W   = cmul(E32, E32);         // E^64
        const float2 W2  = cmul(W, W);
        const float2 W4  = cmul(W2, W2);
        const float2 W8  = cmul(W4, W4);
        const float2 W16 = cmul(W8, W8);
        cst[n * 9 + 0] = Cd;  cst[n * 9 + 1] = E;   cst[n * 9 + 2] = E8;
        cst[n * 9 + 3] = E16; cst[n * 9 + 4] = E32; cst[n * 9 + 5] = W;
        cst[n * 9 + 6] = W4;  cst[n * 9 + 7] = W8;  cst[n * 9 + 8] = W16;
    }
    __syncthreads();

    // ---- generate A (P = Cd*E^i, hi/lo) : thread = (mode n, i-octet q) ----
    {
        const int n = tid & 31;
        const int q = tid >> 5;                    // i = 8q .. 8q+7
        const float2 E = cst[n * 9 + 1];
        float2 z = cst[n * 9 + 0];                 // Cd
        if (q & 1) z = cmul(z, cst[n * 9 + 2]);    // E^8
        if (q & 2) z = cmul(z, cst[n * 9 + 3]);    // E^16
        if (q & 4) z = cmul(z, cst[n * 9 + 4]);    // E^32
        #pragma unroll
        for (int s = 0; s < 8; s++) {
            const int i = q * 8 + s;
            const __nv_bfloat16 rh = __float2bfloat16(z.x);
            const __nv_bfloat16 rl = __float2bfloat16(z.x - __bfloat162float(rh));
            const __nv_bfloat16 ih = __float2bfloat16(z.y);
            const __nv_bfloat16 il = __float2bfloat16(z.y - __bfloat162float(ih));
            Ahi[i * LDA + n]      = rh;
            Ahi[i * LDA + 32 + n] = ih;
            Alo[i * LDA + n]      = rl;
            Alo[i * LDA + 32 + n] = il;
            z = cmul(z, E);
        }
    }

    // ---- generate B (W^j, hi/lo, minus sign on Im) : thread = (n, j-quad q) ----
    {
        const int n = tid & 31;
        const int q = tid >> 5;                    // j = 4q .. 4q+3
        const float2 W = cst[n * 9 + 5];
        float2 w = make_float2(1.0f, 0.0f);
        if (q & 1) w = cst[n * 9 + 6];             // W^4
        if (q & 2) w = cmul(w, cst[n * 9 + 7]);    // W^8
        if (q & 4) w = cmul(w, cst[n * 9 + 8]);    // W^16
        #pragma unroll
        for (int s = 0; s < 4; s++) {
            const int j = q * 4 + s;
            const float re = w.x;
            const float ni = -w.y;
            const __nv_bfloat16 rh = __float2bfloat16(re);
            const __nv_bfloat16 rl = __float2bfloat16(re - __bfloat162float(rh));
            const __nv_bfloat16 ih = __float2bfloat16(ni);
            const __nv_bfloat16 il = __float2bfloat16(ni - __bfloat162float(ih));
            Bhi[j * LDA + n]      = rh;
            Bhi[j * LDA + 32 + n] = ih;
            Blo[j * LDA + n]      = rl;
            Blo[j * LDA + 32 + n] = il;
            w = cmul(w, W);
        }
    }
    __syncthreads();

    // ---- WMMA: warp w owns output tile (it = w&3, jt = w>>2), 16x16 ----
    {
        const int it = wid & 3;                    // m-tile (i = it*16 ..)
        const int jt = wid >> 2;                   // n-tile (j = jt*16 ..)

        wmma::fragment<wmma::matrix_a, 16, 16, 16, __nv_bfloat16, wmma::row_major> af;
        wmma::fragment<wmma::matrix_b, 16, 16, 16, __nv_bfloat16, wmma::col_major> bf;
        wmma::fragment<wmma::accumulator, 16, 16, 16, float> acc;
        wmma::fill_fragment(acc, 0.0f);

        const __nv_bfloat16* As[3] = { Ahi, Alo, Ahi };
        const __nv_bfloat16* Bs[3] = { Bhi, Bhi, Blo };

        #pragma unroll
        for (int p = 0; p < 3; p++) {
            #pragma unroll
            for (int kt = 0; kt < 4; kt++) {
                wmma::load_matrix_sync(af, As[p] + (it * 16) * LDA + kt * 16, LDA);
                wmma::load_matrix_sync(bf, Bs[p] + (jt * 16) * LDA + kt * 16, LDA);
                wmma::mma_sync(acc, af, bf, acc);
            }
        }
        #pragma unroll
        for (int e = 0; e < acc.num_elements; e++) acc.x[e] *= 2.0f;

        // out element (i, j) at out[h*2048 + j*64 + i]  => col-major, ld = 64
        float* op = out + (size_t)h * 2048 + (size_t)(jt * 16) * 64 + it * 16;
        wmma::store_matrix_sync(op, acc, 64, wmma::mem_col_major);
    }
}

// ---------------- generic fallback (any H, N2, L) ----------------
__device__ __forceinline__ float red2pi(float ph) {
    float q = rintf(ph * 0.15915494309f);
    ph = fmaf(q, -6.28125f, ph);
    ph = fmaf(q, -1.93530717e-3f, ph);
    return ph;
}

__global__ void s4d_fallback(
    const float* __restrict__ log_dt,
    const float* __restrict__ Cr,
    const float* __restrict__ logAre,
    const float* __restrict__ Aimag,
    float* __restrict__ out, int H, int N2, int L)
{
    const long long idx = (long long)blockIdx.x * blockDim.x + threadIdx.x;
    if (idx >= (long long)H * L) return;
    const int h = (int)(idx / L);
    const int l = (int)(idx % L);
    const float dt = __expf(log_dt[h]);
    const float lf = (float)l;
    float acc = 0.0f;
    for (int n = 0; n < N2; n++) {
        const float Are = -__expf(logAre[h * N2 + n]);
        const float Ai  = Aimag[h * N2 + n];
        const float dre = Are * dt;
        const float dim = Ai * dt;
        float s1, c1;
        __sincosf(dim, &s1, &c1);
        const float e1 = __expf(dre);
        const float numre = fmaf(e1, c1, -1.0f);
        const float numim = e1 * s1;
        const float inv  = __frcp_rn(fmaf(Are, Are, Ai * Ai));
        const float ccre = Cr[(h * N2 + n) * 2 + 0];
        const float ccim = Cr[(h * N2 + n) * 2 + 1];
        const float tre = ccre * numre - ccim * numim;
        const float tim = ccre * numim + ccim * numre;
        const float cdre = (tre * Are + tim * Ai) * inv;
        const float cdim = (tim * Are - tre * Ai) * inv;
        const float ph = red2pi(dim * lf);
        float s, c;
        __sincosf(ph, &s, &c);
        const float r = __expf(dre * lf);
        acc += r * (cdre * c - cdim * s);
    }
    out[idx] = 2.0f * acc;
}

extern "C" void kernel_launch(void* const* d_in, const int* in_sizes, int n_in,
                              void* d_out, int out_size)
{
    const float* log_dt = (const float*)d_in[0];
    const float* Cr     = (const float*)d_in[1];
    const float* lar    = (const float*)d_in[2];
    const float* aim    = (const float*)d_in[3];
    float* out = (float*)d_out;

    const int H  = in_sizes[0];
    const int N2 = (H > 0) ? in_sizes[2] / H : 0;
    const int L  = (H > 0) ? out_size / H : 0;

    if (N2 == 32 && L == 2048) {
        s4d_wmma<<<H, 256>>>(log_dt, Cr, lar, aim, out);
    } else {
        const long long total = (long long)H * L;
        const int blocks = (int)((total + 127) / 128);
        s4d_fallback<<<blocks, 128>>>(log_dt, Cr, lar, aim, out, H, N2, L);
    }
}

// round 5
// speedup vs baseline: 1.3047x; 1.0339x over previous
#include <cuda_runtime.h>
#include <cuda_bf16.h>
#include <mma.h>
#include <cstdint>

using namespace nvcuda;

__device__ __forceinline__ float2 cmul(float2 a, float2 b) {
    return make_float2(fmaf(a.x, b.x, -a.y * b.y), fmaf(a.x, b.y, a.y * b.x));
}

// ============================ WMMA kernel ============================
// One CTA (256 thr) per head h. out[h, 64j+i] = 2*sum_n [ReP*ReW^j - ImP*ImW^j]
//   P = Cd*E^i, E = exp(dtA), W = E^64.
// Real GEMM M=64 (i) x N=32 (j) x K=64, k-interleaved: k=2n -> Re, k=2n+1 -> Im
// (with -Im on the B side). bf16 hi/lo split, 3 passes:
//   acc = Ahi*Bhi + Alo*Bhi + Ahi*Blo   (lo*lo dropped, ~2^-16 relative).
// All per-mode constants are computed redundantly per-warp (lane = mode) in
// registers -- no shared const stage, single __syncthreads before the MMA.

static constexpr int LDA = 72;   // padded stride (144 B) to dodge ldsm conflicts

__global__ __launch_bounds__(256, 5)
void s4d_wmma(const float* __restrict__ log_dt,
              const float* __restrict__ Cr,
              const float* __restrict__ logAre,
              const float* __restrict__ Aimag,
              float* __restrict__ out)
{
    __shared__ __nv_bfloat16 Ahi[64 * LDA];   // 9216 B
    __shared__ __nv_bfloat16 Alo[64 * LDA];   // 9216 B
    __shared__ __nv_bfloat16 Bhi[32 * LDA];   // 4608 B
    __shared__ __nv_bfloat16 Blo[32 * LDA];   // 4608 B

    const int h   = blockIdx.x;
    const int tid = threadIdx.x;
    const int wid = tid >> 5;
    const int lid = tid & 31;

    // ---- per-lane (mode) constants, redundant per warp ----
    const int n = lid;
    const float dt  = __expf(log_dt[h]);
    const float Are = -__expf(logAre[h * 32 + n]);
    const float Ai  = Aimag[h * 32 + n];
    const float dre = Are * dt;
    const float dim = Ai * dt;                 // |dim| <= ~9.8
    float sn, cs;
    __sincosf(dim, &sn, &cs);
    const float e1 = __expf(dre);
    const float2 E = make_float2(e1 * cs, e1 * sn);
    const float inv = __frcp_rn(fmaf(Are, Are, Ai * Ai));
    const float ccre = Cr[(h * 32 + n) * 2 + 0];
    const float ccim = Cr[(h * 32 + n) * 2 + 1];
    const float numre = E.x - 1.0f, numim = E.y;
    const float tre = ccre * numre - ccim * numim;
    const float tim = ccre * numim + ccim * numre;
    const float2 Cd = make_float2((tre * Are + tim * Ai) * inv,
                                  (tim * Are - tre * Ai) * inv);

    const float2 E2  = cmul(E, E);
    const float2 E4  = cmul(E2, E2);
    const float2 E8  = cmul(E4, E4);
    const float2 E16 = cmul(E8, E8);
    const float2 E32 = cmul(E16, E16);
    const float2 W   = cmul(E32, E32);         // E^64

    // ---- generate A rows i = 8*wid .. 8*wid+7 ----
    {
        float2 base = Cd;
        if (wid & 1) base = cmul(base, E8);
        if (wid & 2) base = cmul(base, E16);
        if (wid & 4) base = cmul(base, E32);
        float2 Ep[8];
        Ep[0] = make_float2(1.0f, 0.0f);
        Ep[1] = E;  Ep[2] = E2;  Ep[4] = E4;
        Ep[3] = cmul(E2, E);
        Ep[5] = cmul(E4, E);
        Ep[6] = cmul(E4, E2);
        Ep[7] = cmul(E4, Ep[3]);
        #pragma unroll
        for (int s = 0; s < 8; s++) {
            const float2 z = (s == 0) ? base : cmul(base, Ep[s]);
            const int i = wid * 8 + s;
            const __nv_bfloat16 rh = __float2bfloat16(z.x);
            const __nv_bfloat16 rl = __float2bfloat16(z.x - __bfloat162float(rh));
            const __nv_bfloat16 ih = __float2bfloat16(z.y);
            const __nv_bfloat16 il = __float2bfloat16(z.y - __bfloat162float(ih));
            ((__nv_bfloat162*)(Ahi + i * LDA))[n] = __nv_bfloat162(rh, ih);
            ((__nv_bfloat162*)(Alo + i * LDA))[n] = __nv_bfloat162(rl, il);
        }
    }

    // ---- generate B cols j = 4*wid .. 4*wid+3 (col-major, -Im) ----
    {
        const float2 W2  = cmul(W, W);
        const float2 W4  = cmul(W2, W2);
        const float2 W8  = cmul(W4, W4);
        const float2 W16 = cmul(W8, W8);
        float2 base = make_float2(1.0f, 0.0f);
        if (wid & 1) base = W4;
        if (wid & 2) base = cmul(base, W8);
        if (wid & 4) base = cmul(base, W16);
        float2 Wp[4];
        Wp[0] = make_float2(1.0f, 0.0f);
        Wp[1] = W; Wp[2] = W2; Wp[3] = cmul(W2, W);
        #pragma unroll
        for (int s = 0; s < 4; s++) {
            const float2 w = (s == 0) ? base : cmul(base, Wp[s]);
            const int j = wid * 4 + s;
            const float re = w.x;
            const float ni = -w.y;
            const __nv_bfloat16 rh = __float2bfloat16(re);
            const __nv_bfloat16 rl = __float2bfloat16(re - __bfloat162float(rh));
            const __nv_bfloat16 ih = __float2bfloat16(ni);
            const __nv_bfloat16 il = __float2bfloat16(ni - __bfloat162float(ih));
            ((__nv_bfloat162*)(Bhi + j * LDA))[n] = __nv_bfloat162(rh, ih);
            ((__nv_bfloat162*)(Blo + j * LDA))[n] = __nv_bfloat162(rl, il);
        }
    }
    __syncthreads();

    // ---- WMMA: warp w owns output tile (it = w&3, jt = w>>2), 16x16 ----
    {
        const int it = wid & 3;
        const int jt = wid >> 2;

        wmma::fragment<wmma::matrix_a, 16, 16, 16, __nv_bfloat16, wmma::row_major> af;
        wmma::fragment<wmma::matrix_b, 16, 16, 16, __nv_bfloat16, wmma::col_major> bf;
        wmma::fragment<wmma::accumulator, 16, 16, 16, float> acc;
        wmma::fill_fragment(acc, 0.0f);

        const __nv_bfloat16* As[3] = { Ahi, Alo, Ahi };
        const __nv_bfloat16* Bs[3] = { Bhi, Bhi, Blo };

        #pragma unroll
        for (int p = 0; p < 3; p++) {
            #pragma unroll
            for (int kt = 0; kt < 4; kt++) {
                wmma::load_matrix_sync(af, As[p] + (it * 16) * LDA + kt * 16, LDA);
                wmma::load_matrix_sync(bf, Bs[p] + (jt * 16) * LDA + kt * 16, LDA);
                wmma::mma_sync(acc, af, bf, acc);
            }
        }
        #pragma unroll
        for (int e = 0; e < acc.num_elements; e++) acc.x[e] *= 2.0f;

        float* op = out + (size_t)h * 2048 + (size_t)(jt * 16) * 64 + it * 16;
        wmma::store_matrix_sync(op, acc, 64, wmma::mem_col_major);
    }
}

// ---------------- generic fallback (any H, N2, L) ----------------
__device__ __forceinline__ float red2pi(float ph) {
    float q = rintf(ph * 0.15915494309f);
    ph = fmaf(q, -6.28125f, ph);
    ph = fmaf(q, -1.93530717e-3f, ph);
    return ph;
}

__global__ void s4d_fallback(
    const float* __restrict__ log_dt,
    const float* __restrict__ Cr,
    const float* __restrict__ logAre,
    const float* __restrict__ Aimag,
    float* __restrict__ out, int H, int N2, int L)
{
    const long long idx = (long long)blockIdx.x * blockDim.x + threadIdx.x;
    if (idx >= (long long)H * L) return;
    const int h = (int)(idx / L);
    const int l = (int)(idx % L);
    const float dt = __expf(log_dt[h]);
    const float lf = (float)l;
    float acc = 0.0f;
    for (int n = 0; n < N2; n++) {
        const float Are = -__expf(logAre[h * N2 + n]);
        const float Ai  = Aimag[h * N2 + n];
        const float dre = Are * dt;
        const float dim = Ai * dt;
        float s1, c1;
        __sincosf(dim, &s1, &c1);
        const float e1 = __expf(dre);
        const float numre = fmaf(e1, c1, -1.0f);
        const float numim = e1 * s1;
        const float inv  = __frcp_rn(fmaf(Are, Are, Ai * Ai));
        const float ccre = Cr[(h * N2 + n) * 2 + 0];
        const float ccim = Cr[(h * N2 + n) * 2 + 1];
        const float tre = ccre * numre - ccim * numim;
        const float tim = ccre * numim + ccim * numre;
        const float cdre = (tre * Are + tim * Ai) * inv;
        const float cdim = (tim * Are - tre * Ai) * inv;
        const float ph = red2pi(dim * lf);
        float s, c;
        __sincosf(ph, &s, &c);
        const float r = __expf(dre * lf);
        acc += r * (cdre * c - cdim * s);
    }
    out[idx] = 2.0f * acc;
}

extern "C" void kernel_launch(void* const* d_in, const int* in_sizes, int n_in,
                              void* d_out, int out_size)
{
    const float* log_dt = (const float*)d_in[0];
    const float* Cr     = (const float*)d_in[1];
    const float* lar    = (const float*)d_in[2];
    const float* aim    = (const float*)d_in[3];
    float* out = (float*)d_out;

    const int H  = in_sizes[0];
    const int N2 = (H > 0) ? in_sizes[2] / H : 0;
    const int L  = (H > 0) ? out_size / H : 0;

    if (N2 == 32 && L == 2048) {
        s4d_wmma<<<H, 256>>>(log_dt, Cr, lar, aim, out);
    } else {
        const long long total = (long long)H * L;
        const int blocks = (int)((total + 127) / 128);
        s4d_fallback<<<blocks, 128>>>(log_dt, Cr, lar, aim, out, H, N2, L);
    }
}